// round 1
// baseline (speedup 1.0000x reference)
#include <cuda_runtime.h>

#define HH 1024
#define WW 1024
#define CC 8
#define NN 2
#define PADR 16
#define TH 16
#define TW 64
#define SROWS 48   // TH + 32
#define SCOLS 96   // TW + 32
#define SCH (SROWS*SCOLS)

// ---- device-global scratch / accumulators (no allocations allowed) ----
__device__ __align__(16) float g_scratch[NN*HH*WW];   // |mean_c(ms_o) - pan|
__device__ unsigned int g_minbits;
__device__ unsigned int g_maxbits;
__device__ double g_sum;
__device__ unsigned long long g_cnt;

__global__ void init_k() {
    g_minbits = 0x7F800000u;  // +inf
    g_maxbits = 0u;           // 0.0f (values are >= 0)
    g_sum = 0.0;
    g_cnt = 0ull;
}

// Pass 1: per-pixel gray diff + global min/max
__global__ void __launch_bounds__(256) mask_k(const float* __restrict__ mso,
                                              const float* __restrict__ pan) {
    int t = blockIdx.x * 256 + threadIdx.x;
    int p = t << 2;                 // 4 pixels per thread
    int n = p >> 20;
    int hw = p & 0xFFFFF;

    float4 acc = make_float4(0.f, 0.f, 0.f, 0.f);
#pragma unroll
    for (int c = 0; c < CC; c++) {
        float4 v = *(const float4*)&mso[((size_t)(n * CC + c) << 20) + hw];
        acc.x += v.x; acc.y += v.y; acc.z += v.z; acc.w += v.w;
    }
    float4 pv = *(const float4*)&pan[((size_t)n << 20) + hw];
    float4 g;
    g.x = fabsf(acc.x * 0.125f - pv.x);
    g.y = fabsf(acc.y * 0.125f - pv.y);
    g.z = fabsf(acc.z * 0.125f - pv.z);
    g.w = fabsf(acc.w * 0.125f - pv.w);
    *(float4*)&g_scratch[p] = g;

    float lmin = fminf(fminf(g.x, g.y), fminf(g.z, g.w));
    float lmax = fmaxf(fmaxf(g.x, g.y), fmaxf(g.z, g.w));
#pragma unroll
    for (int o = 16; o; o >>= 1) {
        lmin = fminf(lmin, __shfl_xor_sync(0xffffffffu, lmin, o));
        lmax = fmaxf(lmax, __shfl_xor_sync(0xffffffffu, lmax, o));
    }
    __shared__ float smn[8], smx[8];
    int lane = threadIdx.x & 31, wid = threadIdx.x >> 5;
    if (!lane) { smn[wid] = lmin; smx[wid] = lmax; }
    __syncthreads();
    if (threadIdx.x == 0) {
        float mn = smn[0], mx = smx[0];
#pragma unroll
        for (int i = 1; i < 8; i++) { mn = fminf(mn, smn[i]); mx = fmaxf(mx, smx[i]); }
        atomicMin(&g_minbits, __float_as_uint(mn));
        atomicMax(&g_maxbits, __float_as_uint(mx));
    }
}

// Pass 2: min-shift SAD + masked accumulation
__global__ void __launch_bounds__(256, 1) main_k(const float* __restrict__ ms,
                                                 const float* __restrict__ tgt) {
    extern __shared__ float sT[];   // [CC][SROWS][SCOLS]

    const int n  = blockIdx.z;
    const int h0 = blockIdx.y * TH;
    const int w0 = blockIdx.x * TW;
    const int tx = threadIdx.x;     // 0..15 -> 4 pixels each along w
    const int ty = threadIdx.y;     // 0..15 -> 1 row each
    const int tid = ty * 16 + tx;

    // --- load target tile with reflect padding ---
    const int TOT = CC * SROWS * SCOLS;   // 36864 = 144 * 256
#pragma unroll 4
    for (int e = tid; e < TOT; e += 256) {
        int c   = e / SCH;
        int rem = e - c * SCH;
        int r   = rem / SCOLS;
        int col = rem - r * SCOLS;
        int gr = h0 + r - PADR;
        gr = gr < 0 ? -gr : (gr >= HH ? 2 * HH - 2 - gr : gr);
        int gc = w0 + col - PADR;
        gc = gc < 0 ? -gc : (gc >= WW ? 2 * WW - 2 - gc : gc);
        sT[e] = tgt[(((size_t)n * CC + c) * HH + gr) * WW + gc];
    }
    __syncthreads();

    const int h     = h0 + ty;
    const int wbase = w0 + (tx << 2);

    // ms pixels for this thread: 8 channels x 4 px
    float4 msr[CC];
#pragma unroll
    for (int c = 0; c < CC; c++)
        msr[c] = *(const float4*)&ms[(((size_t)n * CC + c) * HH + h) * WW + wbase];

    float minv[4] = {3.4e38f, 3.4e38f, 3.4e38f, 3.4e38f};

#pragma unroll 1
    for (int di = 0; di < 9; di++) {
        float part[36];
#pragma unroll
        for (int i = 0; i < 36; i++) part[i] = 0.f;

        const int rb = (ty + di * 4) * SCOLS + (tx << 2);
#pragma unroll
        for (int c = 0; c < CC; c++) {
            const float* p = sT + c * SCH + rb;
            const float4 m = msr[c];
#pragma unroll
            for (int dj = 0; dj < 9; dj++) {
                float4 tv = *(const float4*)(p + (dj << 2));
                part[dj * 4 + 0] += fabsf(m.x - tv.x);
                part[dj * 4 + 1] += fabsf(m.y - tv.y);
                part[dj * 4 + 2] += fabsf(m.z - tv.z);
                part[dj * 4 + 3] += fabsf(m.w - tv.w);
            }
        }
#pragma unroll
        for (int dj = 0; dj < 9; dj++) {
            minv[0] = fminf(minv[0], part[dj * 4 + 0]);
            minv[1] = fminf(minv[1], part[dj * 4 + 1]);
            minv[2] = fminf(minv[2], part[dj * 4 + 2]);
            minv[3] = fminf(minv[3], part[dj * 4 + 3]);
        }
    }

    // --- mask + reduce ---
    const float mn  = __uint_as_float(g_minbits);
    const float mx  = __uint_as_float(g_maxbits);
    const float thr = mn + (mx - mn) * (10.0f / 255.0f);

    float4 g = *(const float4*)&g_scratch[((size_t)n << 20) + h * WW + wbase];
    float lsum = 0.f;
    int   lcnt = 0;
    if (g.x > thr) { lsum += minv[0]; lcnt++; }
    if (g.y > thr) { lsum += minv[1]; lcnt++; }
    if (g.z > thr) { lsum += minv[2]; lcnt++; }
    if (g.w > thr) { lsum += minv[3]; lcnt++; }

#pragma unroll
    for (int o = 16; o; o >>= 1) {
        lsum += __shfl_xor_sync(0xffffffffu, lsum, o);
        lcnt += __shfl_xor_sync(0xffffffffu, lcnt, o);
    }
    __shared__ float wsum[8];
    __shared__ int   wcnt[8];
    int lane = tid & 31, wid = tid >> 5;
    if (!lane) { wsum[wid] = lsum; wcnt[wid] = lcnt; }
    __syncthreads();
    if (tid == 0) {
        double bs = 0.0; long long bc = 0;
#pragma unroll
        for (int i = 0; i < 8; i++) { bs += (double)wsum[i]; bc += wcnt[i]; }
        atomicAdd(&g_sum, bs);
        atomicAdd(&g_cnt, (unsigned long long)bc);
    }
}

__global__ void fin_k(float* out) {
    unsigned long long c = g_cnt;
    out[0] = (c > 0ull) ? (float)(g_sum / (double)c) : 0.0f;
}

extern "C" void kernel_launch(void* const* d_in, const int* in_sizes, int n_in,
                              void* d_out, int out_size) {
    const float* ms  = (const float*)d_in[0];
    const float* tgt = (const float*)d_in[1];
    const float* mso = (const float*)d_in[2];
    const float* pan = (const float*)d_in[3];
    float* out = (float*)d_out;

    const int smem = CC * SCH * (int)sizeof(float);   // 147456 B
    cudaFuncSetAttribute(main_k, cudaFuncAttributeMaxDynamicSharedMemorySize, smem);

    init_k<<<1, 1>>>();
    mask_k<<<(NN * HH * WW) / 4 / 256, 256>>>(mso, pan);
    dim3 grid(WW / TW, HH / TH, NN), blk(16, 16);
    main_k<<<grid, blk, smem>>>(ms, tgt);
    fin_k<<<1, 1>>>(out);
}